// round 3
// baseline (speedup 1.0000x reference)
#include <cuda_runtime.h>
#include <math.h>

#define IN_DIM 256
#define OUT_DIM 256
#define NHEAD 8
#define DK 32
#define MAXN 50000
#define MAXE 800000

// ---------------- scratch (static device allocations; no cudaMalloc) --------
__device__ float g_TE [MAXN * IN_DIM];   // concatenated text embeddings
__device__ float g_Q  [MAXN * OUT_DIM];
__device__ float g_Kr [MAXN * OUT_DIM];  // K + relation_emb (folded via bias2)
__device__ float g_V  [MAXN * OUT_DIM];
__device__ float g_agg[MAXN * OUT_DIM];  // attention aggregation result
__device__ int   g_deg[MAXN];
__device__ int   g_ptr[MAXN + 1];
__device__ int   g_cur[MAXN];
__device__ int   g_src[MAXE];            // source node per CSR slot

// ---------------- small utility kernels -------------------------------------
__global__ void concat_kernel(const float4* __restrict__ user,
                              const float4* __restrict__ item,
                              int nu4, int total4) {
    float4* te = reinterpret_cast<float4*>(g_TE);
    for (int i = blockIdx.x * blockDim.x + threadIdx.x; i < total4;
         i += gridDim.x * blockDim.x) {
        te[i] = (i < nu4) ? user[i] : item[i - nu4];
    }
}

__global__ void zero_deg_kernel(int n) {
    for (int i = blockIdx.x * blockDim.x + threadIdx.x; i < n;
         i += gridDim.x * blockDim.x)
        g_deg[i] = 0;
}

__global__ void count_kernel(const int* __restrict__ col, int E) {
    for (int e = blockIdx.x * blockDim.x + threadIdx.x; e < E;
         e += gridDim.x * blockDim.x)
        atomicAdd(&g_deg[col[e]], 1);
}

// single-block exclusive scan of g_deg[0..n) -> g_ptr / g_cur, g_ptr[n]=E
__global__ void scan_kernel(int n) {
    __shared__ int sh[1024];
    __shared__ int carry;
    const int tid = threadIdx.x;
    if (tid == 0) carry = 0;
    __syncthreads();
    for (int base = 0; base < n; base += 1024) {
        int i = base + tid;
        int v = (i < n) ? g_deg[i] : 0;
        sh[tid] = v;
        __syncthreads();
        for (int off = 1; off < 1024; off <<= 1) {
            int t = (tid >= off) ? sh[tid - off] : 0;
            __syncthreads();
            sh[tid] += t;
            __syncthreads();
        }
        int excl = sh[tid] - v;
        if (i < n) {
            g_ptr[i] = carry + excl;
            g_cur[i] = carry + excl;
        }
        __syncthreads();
        if (tid == 0) carry += sh[1023];
        __syncthreads();
    }
    if (threadIdx.x == 0) g_ptr[n] = carry;
}

__global__ void scatter_kernel(const int* __restrict__ row,
                               const int* __restrict__ col, int E) {
    for (int e = blockIdx.x * blockDim.x + threadIdx.x; e < E;
         e += gridDim.x * blockDim.x) {
        int pos = atomicAdd(&g_cur[col[e]], 1);
        g_src[pos] = row[e];
    }
}

// ---------------- SGEMM: C[M,256] = A[M,256] @ W[256,256]^T + bias (+bias2) --
// 128x128 tile, BK=16, 256 threads, 8x8 per thread.
__global__ void __launch_bounds__(256)
sgemm_bias_kernel(const float* __restrict__ A, const float* __restrict__ W,
                  const float* __restrict__ bias, const float* __restrict__ bias2,
                  float* __restrict__ C, int M) {
    __shared__ float As[16][128];
    __shared__ float Ws[16][128];
    const int tid = threadIdx.x;
    const int bm = blockIdx.x * 128;
    const int bn = blockIdx.y * 128;
    const int lr = tid >> 1;        // 0..127 : tile row for loads
    const int lc = (tid & 1) * 8;   // 0 or 8 : k-offset for loads
    const int ty = tid >> 4;        // 0..15
    const int tx = tid & 15;        // 0..15

    float acc[8][8];
#pragma unroll
    for (int i = 0; i < 8; i++)
#pragma unroll
        for (int j = 0; j < 8; j++) acc[i][j] = 0.f;

    const int arow = bm + lr;
    const float* Aptr = A + (size_t)arow * IN_DIM;
    const float* Wptr = W + (size_t)(bn + lr) * IN_DIM;

    for (int k0 = 0; k0 < IN_DIM; k0 += 16) {
        float4 a0, a1;
        if (arow < M) {
            a0 = *(const float4*)(Aptr + k0 + lc);
            a1 = *(const float4*)(Aptr + k0 + lc + 4);
        } else {
            a0 = make_float4(0.f, 0.f, 0.f, 0.f);
            a1 = a0;
        }
        float4 w0 = *(const float4*)(Wptr + k0 + lc);
        float4 w1 = *(const float4*)(Wptr + k0 + lc + 4);
        __syncthreads();
        As[lc + 0][lr] = a0.x; As[lc + 1][lr] = a0.y;
        As[lc + 2][lr] = a0.z; As[lc + 3][lr] = a0.w;
        As[lc + 4][lr] = a1.x; As[lc + 5][lr] = a1.y;
        As[lc + 6][lr] = a1.z; As[lc + 7][lr] = a1.w;
        Ws[lc + 0][lr] = w0.x; Ws[lc + 1][lr] = w0.y;
        Ws[lc + 2][lr] = w0.z; Ws[lc + 3][lr] = w0.w;
        Ws[lc + 4][lr] = w1.x; Ws[lc + 5][lr] = w1.y;
        Ws[lc + 6][lr] = w1.z; Ws[lc + 7][lr] = w1.w;
        __syncthreads();
#pragma unroll
        for (int k = 0; k < 16; k++) {
            float a[8], b[8];
            *(float4*)&a[0] = *(const float4*)&As[k][ty * 8];
            *(float4*)&a[4] = *(const float4*)&As[k][ty * 8 + 4];
            *(float4*)&b[0] = *(const float4*)&Ws[k][tx * 8];
            *(float4*)&b[4] = *(const float4*)&Ws[k][tx * 8 + 4];
#pragma unroll
            for (int i = 0; i < 8; i++)
#pragma unroll
                for (int j = 0; j < 8; j++) acc[i][j] += a[i] * b[j];
        }
    }

#pragma unroll
    for (int j = 0; j < 8; j++) {
        int o = bn + tx * 8 + j;
        float bb = bias[o] + (bias2 ? bias2[o] : 0.f);
#pragma unroll
        for (int i = 0; i < 8; i++) {
            int m = bm + ty * 8 + i;
            if (m < M) C[(size_t)m * OUT_DIM + o] = acc[i][j] + bb;
        }
    }
}

// ---------------- per-destination-node attention (online softmax) -----------
// block = destination node n; warp w = head; lane l = dim within head.
__global__ void __launch_bounds__(256)
attn_kernel(const float* __restrict__ Q, const float* __restrict__ Kr,
            const float* __restrict__ V, float* __restrict__ agg, int N) {
    const int n = blockIdx.x;
    if (n >= N) return;
    const int w = threadIdx.x >> 5;   // head
    const int l = threadIdx.x & 31;   // dim within head
    const int beg = g_ptr[n];
    const int end = g_ptr[n + 1];
    const int d = w * DK + l;

    const float qv = Q[(size_t)n * OUT_DIM + d];
    const float inv_sqrt_dk = 0.17677669529663689f;  // 1/sqrt(32)

    float m = -INFINITY;
    float s = 0.f;
    float acc = 0.f;

    for (int i = beg; i < end; i++) {
        int r = g_src[i];
        float kv = Kr[(size_t)r * OUT_DIM + d];
        float vv = V[(size_t)r * OUT_DIM + d];
        float p = qv * kv;
        p += __shfl_xor_sync(0xffffffffu, p, 16);
        p += __shfl_xor_sync(0xffffffffu, p, 8);
        p += __shfl_xor_sync(0xffffffffu, p, 4);
        p += __shfl_xor_sync(0xffffffffu, p, 2);
        p += __shfl_xor_sync(0xffffffffu, p, 1);
        float x = p * inv_sqrt_dk;
        float nm = fmaxf(m, x);
        float scale = __expf(m - nm);   // 0 on first iteration (m=-inf)
        float ex = __expf(x - nm);
        s = s * scale + ex;
        acc = acc * scale + ex * vv;
        m = nm;
    }
    agg[(size_t)n * OUT_DIM + d] = (s > 0.f) ? (acc / s) : 0.f;
}

// ---------------- launch ----------------------------------------------------
extern "C" void kernel_launch(void* const* d_in, const int* in_sizes, int n_in,
                              void* d_out, int out_size) {
    const float* x    = (const float*)d_in[0];
    const int*   row  = (const int*)  d_in[1];
    const int*   col  = (const int*)  d_in[2];
    const float* rel  = (const float*)d_in[3];
    const float* user = (const float*)d_in[4];
    const float* item = (const float*)d_in[5];
    const float* Wq   = (const float*)d_in[6];
    const float* bq   = (const float*)d_in[7];
    const float* Wk   = (const float*)d_in[8];
    const float* bk   = (const float*)d_in[9];
    const float* Wv   = (const float*)d_in[10];
    const float* bv   = (const float*)d_in[11];
    const float* Wo   = (const float*)d_in[12];
    const float* bo   = (const float*)d_in[13];
    float* out = (float*)d_out;

    const int N  = in_sizes[0] / IN_DIM;
    const int E  = in_sizes[1];
    const int NU = in_sizes[4] / IN_DIM;

    // resolve device-global addresses (host-side queries; no allocation)
    float *dTE, *dQ, *dKr, *dV, *dAgg;
    cudaGetSymbolAddress((void**)&dTE,  g_TE);
    cudaGetSymbolAddress((void**)&dQ,   g_Q);
    cudaGetSymbolAddress((void**)&dKr,  g_Kr);
    cudaGetSymbolAddress((void**)&dV,   g_V);
    cudaGetSymbolAddress((void**)&dAgg, g_agg);

    // 1. concat text embeddings
    {
        int total4 = N * (IN_DIM / 4);
        int nu4 = NU * (IN_DIM / 4);
        concat_kernel<<<2048, 256>>>((const float4*)user, (const float4*)item,
                                     nu4, total4);
    }

    // 2. CSR build by destination (col)
    zero_deg_kernel<<<(N + 255) / 256, 256>>>(N);
    count_kernel<<<(E + 255) / 256, 256>>>(col, E);
    scan_kernel<<<1, 1024>>>(N);
    scatter_kernel<<<(E + 255) / 256, 256>>>(row, col, E);

    // 3. projections
    dim3 g((N + 127) / 128, OUT_DIM / 128);
    sgemm_bias_kernel<<<g, 256>>>(dTE, Wq, bq, nullptr, dQ,  N);
    sgemm_bias_kernel<<<g, 256>>>(dTE, Wk, bk, rel,     dKr, N);  // K + rel folded
    sgemm_bias_kernel<<<g, 256>>>(x,   Wv, bv, nullptr, dV,  N);

    // 4. per-node attention with online softmax
    attn_kernel<<<N, 256>>>(dQ, dKr, dV, dAgg, N);

    // 5. output projection -> d_out
    sgemm_bias_kernel<<<g, 256>>>(dAgg, Wo, bo, nullptr, out, N);
}

// round 5
// speedup vs baseline: 2.0156x; 2.0156x over previous
#include <cuda_runtime.h>
#include <cuda_bf16.h>
#include <math.h>
#include <stdint.h>

#define IN_DIM 256
#define OUT_DIM 256
#define DK 32
#define MAXN 50000
#define MAXE 800000

// ---------------- static device scratch (no cudaMalloc anywhere) ------------
__device__ __nv_bfloat16 g_TEh[MAXN * IN_DIM];
__device__ __nv_bfloat16 g_TEl[MAXN * IN_DIM];
__device__ __nv_bfloat16 g_Xh [MAXN * IN_DIM];
__device__ __nv_bfloat16 g_Xl [MAXN * IN_DIM];
__device__ __nv_bfloat16 g_AGh[MAXN * OUT_DIM];
__device__ __nv_bfloat16 g_AGl[MAXN * OUT_DIM];
__device__ __nv_bfloat16 g_Wh [4 * OUT_DIM * IN_DIM];
__device__ __nv_bfloat16 g_Wl [4 * OUT_DIM * IN_DIM];
__device__ float g_Q  [MAXN * OUT_DIM];
__device__ float g_Kr [MAXN * OUT_DIM];
__device__ float g_V  [MAXN * OUT_DIM];
__device__ float g_agg[MAXN * OUT_DIM];
__device__ int   g_deg[MAXN];
__device__ int   g_ptr[MAXN + 1];
__device__ int   g_cur[MAXN];
__device__ int   g_src[MAXE];
__device__ int   g_bsum[128];

// ---------------- asm helpers (family-common: sm_80+) -------------------------
__device__ __forceinline__ uint32_t smem_u32(const void* p) {
    uint32_t a;
    asm("{ .reg .u64 t; cvta.to.shared.u64 t, %1; cvt.u32.u64 %0, t; }"
        : "=r"(a) : "l"(p));
    return a;
}
__device__ __forceinline__ void cp16(uint32_t dst, const void* src, uint32_t bytes) {
    asm volatile("cp.async.cg.shared.global [%0], [%1], 16, %2;"
                 :: "r"(dst), "l"(src), "r"(bytes));
}
#define CP_COMMIT() asm volatile("cp.async.commit_group;" ::: "memory")
#define CP_WAIT(n)  asm volatile("cp.async.wait_group %0;" :: "n"(n) : "memory")

__device__ __forceinline__ void ldm_x4(uint32_t* r, uint32_t addr) {
    asm volatile("ldmatrix.sync.aligned.m8n8.x4.shared.b16 {%0,%1,%2,%3}, [%4];"
                 : "=r"(r[0]), "=r"(r[1]), "=r"(r[2]), "=r"(r[3]) : "r"(addr));
}
__device__ __forceinline__ void ldm_x2(uint32_t* r, uint32_t addr) {
    asm volatile("ldmatrix.sync.aligned.m8n8.x2.shared.b16 {%0,%1}, [%2];"
                 : "=r"(r[0]), "=r"(r[1]) : "r"(addr));
}
__device__ __forceinline__ void mma_bf16(float* c, const uint32_t* a, const uint32_t* b) {
    asm volatile("mma.sync.aligned.m16n8k16.row.col.f32.bf16.bf16.f32 "
                 "{%0,%1,%2,%3}, {%4,%5,%6,%7}, {%8,%9}, {%0,%1,%2,%3};"
                 : "+f"(c[0]), "+f"(c[1]), "+f"(c[2]), "+f"(c[3])
                 : "r"(a[0]), "r"(a[1]), "r"(a[2]), "r"(a[3]), "r"(b[0]), "r"(b[1]));
}

// ---------------- split-bf16 conversion kernels -------------------------------
__device__ __forceinline__ void split2(float x, float y,
                                       __nv_bfloat162& hi, __nv_bfloat162& lo) {
    __nv_bfloat16 hx = __float2bfloat16(x), hy = __float2bfloat16(y);
    __nv_bfloat16 lx = __float2bfloat16(x - __bfloat162float(hx));
    __nv_bfloat16 ly = __float2bfloat16(y - __bfloat162float(hy));
    hi = __nv_bfloat162(hx, hy);
    lo = __nv_bfloat162(lx, ly);
}
__global__ void cvt_split_kernel(const float4* __restrict__ src,
                                 __nv_bfloat162* __restrict__ hi,
                                 __nv_bfloat162* __restrict__ lo, int n4) {
    for (int i = blockIdx.x * blockDim.x + threadIdx.x; i < n4;
         i += gridDim.x * blockDim.x) {
        float4 v = src[i];
        split2(v.x, v.y, hi[2 * i],     lo[2 * i]);
        split2(v.z, v.w, hi[2 * i + 1], lo[2 * i + 1]);
    }
}
__global__ void cvt_split_te_kernel(const float4* __restrict__ user,
                                    const float4* __restrict__ item,
                                    int nu4, int total4) {
    __nv_bfloat162* hi = reinterpret_cast<__nv_bfloat162*>(g_TEh);
    __nv_bfloat162* lo = reinterpret_cast<__nv_bfloat162*>(g_TEl);
    for (int i = blockIdx.x * blockDim.x + threadIdx.x; i < total4;
         i += gridDim.x * blockDim.x) {
        float4 v = (i < nu4) ? user[i] : item[i - nu4];
        split2(v.x, v.y, hi[2 * i],     lo[2 * i]);
        split2(v.z, v.w, hi[2 * i + 1], lo[2 * i + 1]);
    }
}

// ---------------- CSR build ----------------------------------------------------
__global__ void zero_deg_kernel(int n) {
    for (int i = blockIdx.x * blockDim.x + threadIdx.x; i < n;
         i += gridDim.x * blockDim.x)
        g_deg[i] = 0;
}
__global__ void count_kernel(const int* __restrict__ col, int E) {
    for (int e = blockIdx.x * blockDim.x + threadIdx.x; e < E;
         e += gridDim.x * blockDim.x)
        atomicAdd(&g_deg[col[e]], 1);
}
__global__ void scan_partial_kernel(int n) {
    __shared__ int sh[1024];
    int i = blockIdx.x * 1024 + threadIdx.x;
    int v = (i < n) ? g_deg[i] : 0;
    sh[threadIdx.x] = v;
    __syncthreads();
    for (int off = 1; off < 1024; off <<= 1) {
        int t = (threadIdx.x >= off) ? sh[threadIdx.x - off] : 0;
        __syncthreads();
        sh[threadIdx.x] += t;
        __syncthreads();
    }
    if (i < n) g_ptr[i] = sh[threadIdx.x] - v;
    if (threadIdx.x == 1023) g_bsum[blockIdx.x] = sh[1023];
}
__global__ void scan_bsums_kernel(int nb) {
    if (threadIdx.x == 0) {
        int s = 0;
        for (int b = 0; b < nb; b++) { int t = g_bsum[b]; g_bsum[b] = s; s += t; }
    }
}
__global__ void scan_add_kernel(int n, int E) {
    int i = blockIdx.x * blockDim.x + threadIdx.x;
    if (i < n) {
        int p = g_ptr[i] + g_bsum[i >> 10];
        g_ptr[i] = p;
        g_cur[i] = p;
    }
    if (i == 0) g_ptr[n] = E;
}
__global__ void scatter_kernel(const int* __restrict__ row,
                               const int* __restrict__ col, int E) {
    for (int e = blockIdx.x * blockDim.x + threadIdx.x; e < E;
         e += gridDim.x * blockDim.x) {
        int pos = atomicAdd(&g_cur[col[e]], 1);
        g_src[pos] = row[e];
    }
}

// ---------------- 3M-split bf16 HMMA GEMM -------------------------------------
// C[M,256] = A[M,256] @ W[256,256]^T + bias (+bias2), fp32-equivalent accuracy.
// Logical K = 768 (3 segments: Ah*Wh, Ah*Wl, Al*Wh), 12 k-tiles of BK=64.
// CTA: 128x128, 8 warps of 64x32. 2-stage cp.async pipeline.
#define NKT 12
#define GEMM_SMEM (4 * 16384)

__global__ void __launch_bounds__(256, 2)
gemm3m_kernel(const __nv_bfloat16* __restrict__ Ah, const __nv_bfloat16* __restrict__ Al,
              const __nv_bfloat16* __restrict__ Wh, const __nv_bfloat16* __restrict__ Wl,
              const float* __restrict__ bias, const float* __restrict__ bias2,
              float* __restrict__ C, int M) {
    extern __shared__ char smem[];
    const uint32_t sb = smem_u32(smem);
    // stage s: A at sb + s*16384, B at sb + 32768 + s*16384
    const int tid = threadIdx.x, wid = tid >> 5, lid = tid & 31;
    const int bm = blockIdx.x * 128;
    const int bn = blockIdx.y * 128;
    const int wm = (wid >> 2) * 64;     // warp m-offset in tile
    const int wn = (wid & 3) * 32;      // warp n-offset in tile

    float acc[4][4][4];
#pragma unroll
    for (int i = 0; i < 4; i++)
#pragma unroll
        for (int j = 0; j < 4; j++)
#pragma unroll
            for (int k = 0; k < 4; k++) acc[i][j][k] = 0.f;

    auto load_tile = [&](int kt, int stage) {
        const int seg = kt >> 2;
        const int koff = (kt & 3) * 64;           // k-offset in elements
        const __nv_bfloat16* As = (seg == 2) ? Al : Ah;
        const __nv_bfloat16* Ws = (seg == 1) ? Wl : Wh;
        const uint32_t uA = sb + stage * 16384;
        const uint32_t uB = sb + 32768 + stage * 16384;
        // A: 128 rows x 8 chunks of 16B
#pragma unroll
        for (int i = tid; i < 1024; i += 256) {
            int r = i >> 3, c = i & 7;
            int grow = bm + r;
            const char* g = (const char*)As + (size_t)grow * 512 + koff * 2 + c * 16;
            uint32_t d = uA + r * 128 + ((c ^ (r & 7)) << 4);
            cp16(d, g, (grow < M) ? 16u : 0u);
        }
        // B: 128 rows (n) x 8 chunks
#pragma unroll
        for (int i = tid; i < 1024; i += 256) {
            int r = i >> 3, c = i & 7;
            const char* g = (const char*)Ws + (size_t)(bn + r) * 512 + koff * 2 + c * 16;
            uint32_t d = uB + r * 128 + ((c ^ (r & 7)) << 4);
            cp16(d, g, 16u);
        }
        CP_COMMIT();
    };

    load_tile(0, 0);

    for (int kt = 0; kt < NKT; kt++) {
        const int st = kt & 1;
        if (kt + 1 < NKT) {
            load_tile(kt + 1, (kt + 1) & 1);
            CP_WAIT(1);
        } else {
            CP_WAIT(0);
        }
        __syncthreads();

        const uint32_t uA = sb + st * 16384;
        const uint32_t uB = sb + 32768 + st * 16384;
#pragma unroll
        for (int ks = 0; ks < 4; ks++) {
            uint32_t a[4][4], b[4][2];
#pragma unroll
            for (int ma = 0; ma < 4; ma++) {
                int ar = wm + ma * 16 + (lid & 15);
                int ch = ks * 2 + (lid >> 4);
                ldm_x4(a[ma], uA + ar * 128 + ((ch ^ (ar & 7)) << 4));
            }
#pragma unroll
            for (int na = 0; na < 4; na++) {
                int nr = wn + na * 8 + (lid & 7);
                int ch = ks * 2 + ((lid >> 3) & 1);
                ldm_x2(b[na], uB + nr * 128 + ((ch ^ (nr & 7)) << 4));
            }
#pragma unroll
            for (int ma = 0; ma < 4; ma++)
#pragma unroll
                for (int na = 0; na < 4; na++)
                    mma_bf16(acc[ma][na], a[ma], b[na]);
        }
        __syncthreads();
    }

    // epilogue
    const int g = lid >> 2;
    const int tg = (lid & 3) * 2;
#pragma unroll
    for (int ma = 0; ma < 4; ma++) {
        int mr = bm + wm + ma * 16 + g;
#pragma unroll
        for (int na = 0; na < 4; na++) {
            int nc = bn + wn + na * 8 + tg;
            float b0 = bias[nc], b1 = bias[nc + 1];
            if (bias2) { b0 += bias2[nc]; b1 += bias2[nc + 1]; }
            if (mr < M)
                *(float2*)(C + (size_t)mr * OUT_DIM + nc) =
                    make_float2(acc[ma][na][0] + b0, acc[ma][na][1] + b1);
            if (mr + 8 < M)
                *(float2*)(C + (size_t)(mr + 8) * OUT_DIM + nc) =
                    make_float2(acc[ma][na][2] + b0, acc[ma][na][3] + b1);
        }
    }
}

// ---------------- per-destination-node attention (online softmax) -------------
__global__ void __launch_bounds__(256)
attn_kernel(const float* __restrict__ Q, const float* __restrict__ Kr,
            const float* __restrict__ V, float* __restrict__ agg, int N) {
    const int n = blockIdx.x;
    if (n >= N) return;
    const int w = threadIdx.x >> 5;
    const int l = threadIdx.x & 31;
    const int beg = g_ptr[n];
    const int end = g_ptr[n + 1];
    const int d = w * DK + l;

    const float qv = Q[(size_t)n * OUT_DIM + d];
    const float inv_sqrt_dk = 0.17677669529663689f;

    float m = -INFINITY, s = 0.f, acc = 0.f;
    for (int i = beg; i < end; i++) {
        int r = g_src[i];
        float kv = Kr[(size_t)r * OUT_DIM + d];
        float vv = V[(size_t)r * OUT_DIM + d];
        float p = qv * kv;
        p += __shfl_xor_sync(0xffffffffu, p, 16);
        p += __shfl_xor_sync(0xffffffffu, p, 8);
        p += __shfl_xor_sync(0xffffffffu, p, 4);
        p += __shfl_xor_sync(0xffffffffu, p, 2);
        p += __shfl_xor_sync(0xffffffffu, p, 1);
        float x = p * inv_sqrt_dk;
        float nm = fmaxf(m, x);
        float scale = __expf(m - nm);
        float ex = __expf(x - nm);
        s = s * scale + ex;
        acc = acc * scale + ex * vv;
        m = nm;
    }
    agg[(size_t)n * OUT_DIM + d] = (s > 0.f) ? (acc / s) : 0.f;
}

// ---------------- launch --------------------------------------------------------
extern "C" void kernel_launch(void* const* d_in, const int* in_sizes, int n_in,
                              void* d_out, int out_size) {
    const float* x    = (const float*)d_in[0];
    const int*   row  = (const int*)  d_in[1];
    const int*   col  = (const int*)  d_in[2];
    const float* rel  = (const float*)d_in[3];
    const float* user = (const float*)d_in[4];
    const float* item = (const float*)d_in[5];
    const float* Wq   = (const float*)d_in[6];
    const float* bq   = (const float*)d_in[7];
    const float* Wk   = (const float*)d_in[8];
    const float* bk   = (const float*)d_in[9];
    const float* Wv   = (const float*)d_in[10];
    const float* bv   = (const float*)d_in[11];
    const float* Wo   = (const float*)d_in[12];
    const float* bo   = (const float*)d_in[13];
    float* out = (float*)d_out;

    const int N  = in_sizes[0] / IN_DIM;
    const int E  = in_sizes[1];
    const int NU = in_sizes[4] / IN_DIM;

    float *dQ, *dKr, *dV, *dAgg;
    __nv_bfloat16 *dTEh, *dTEl, *dXh, *dXl, *dAGh, *dAGl, *dWh, *dWl;
    cudaGetSymbolAddress((void**)&dQ,   g_Q);
    cudaGetSymbolAddress((void**)&dKr,  g_Kr);
    cudaGetSymbolAddress((void**)&dV,   g_V);
    cudaGetSymbolAddress((void**)&dAgg, g_agg);
    cudaGetSymbolAddress((void**)&dTEh, g_TEh);
    cudaGetSymbolAddress((void**)&dTEl, g_TEl);
    cudaGetSymbolAddress((void**)&dXh,  g_Xh);
    cudaGetSymbolAddress((void**)&dXl,  g_Xl);
    cudaGetSymbolAddress((void**)&dAGh, g_AGh);
    cudaGetSymbolAddress((void**)&dAGl, g_AGl);
    cudaGetSymbolAddress((void**)&dWh,  g_Wh);
    cudaGetSymbolAddress((void**)&dWl,  g_Wl);

    cudaFuncSetAttribute(gemm3m_kernel,
                         cudaFuncAttributeMaxDynamicSharedMemorySize, GEMM_SMEM);

    // 1. split-bf16 conversions
    {
        int total4 = N * (IN_DIM / 4);
        int nu4 = NU * (IN_DIM / 4);
        cvt_split_te_kernel<<<1024, 256>>>((const float4*)user, (const float4*)item,
                                           nu4, total4);
        cvt_split_kernel<<<1024, 256>>>((const float4*)x,
                                        (__nv_bfloat162*)dXh, (__nv_bfloat162*)dXl,
                                        total4);
        int w4 = OUT_DIM * IN_DIM / 4;
        cvt_split_kernel<<<64, 256>>>((const float4*)Wq,
            (__nv_bfloat162*)(dWh + 0 * 65536), (__nv_bfloat162*)(dWl + 0 * 65536), w4);
        cvt_split_kernel<<<64, 256>>>((const float4*)Wk,
            (__nv_bfloat162*)(dWh + 1 * 65536), (__nv_bfloat162*)(dWl + 1 * 65536), w4);
        cvt_split_kernel<<<64, 256>>>((const float4*)Wv,
            (__nv_bfloat162*)(dWh + 2 * 65536), (__nv_bfloat162*)(dWl + 2 * 65536), w4);
        cvt_split_kernel<<<64, 256>>>((const float4*)Wo,
            (__nv_bfloat162*)(dWh + 3 * 65536), (__nv_bfloat162*)(dWl + 3 * 65536), w4);
    }

    // 2. CSR build by destination (col)
    zero_deg_kernel<<<(N + 255) / 256, 256>>>(N);
    count_kernel<<<(E + 255) / 256, 256>>>(col, E);
    int nb = (N + 1023) / 1024;
    scan_partial_kernel<<<nb, 1024>>>(N);
    scan_bsums_kernel<<<1, 32>>>(nb);
    scan_add_kernel<<<(N + 255) / 256, 256>>>(N, E);
    scatter_kernel<<<(E + 255) / 256, 256>>>(row, col, E);

    // 3. projections (3M-split HMMA)
    dim3 gg((N + 127) / 128, 2);
    gemm3m_kernel<<<gg, 256, GEMM_SMEM>>>(dTEh, dTEl, dWh + 0 * 65536, dWl + 0 * 65536,
                                          bq, nullptr, dQ,  N);
    gemm3m_kernel<<<gg, 256, GEMM_SMEM>>>(dTEh, dTEl, dWh + 1 * 65536, dWl + 1 * 65536,
                                          bk, rel,     dKr, N);
    gemm3m_kernel<<<gg, 256, GEMM_SMEM>>>(dXh,  dXl,  dWh + 2 * 65536, dWl + 2 * 65536,
                                          bv, nullptr, dV,  N);

    // 4. attention
    attn_kernel<<<N, 256>>>(dQ, dKr, dV, dAgg, N);

    // 5. split agg, output projection
    cvt_split_kernel<<<1024, 256>>>((const float4*)dAgg,
                                    (__nv_bfloat162*)dAGh, (__nv_bfloat162*)dAGl,
                                    N * (OUT_DIM / 4));
    gemm3m_kernel<<<gg, 256, GEMM_SMEM>>>(dAGh, dAGl, dWh + 3 * 65536, dWl + 3 * 65536,
                                          bo, nullptr, out, N);
}

// round 6
// speedup vs baseline: 2.6532x; 1.3163x over previous
#include <cuda_runtime.h>
#include <cuda_bf16.h>
#include <cuda_fp16.h>
#include <math.h>
#include <stdint.h>

#define IN_DIM 256
#define OUT_DIM 256
#define DK 32
#define MAXN 50000
#define MAXE 800000

// ---------------- static device scratch (no cudaMalloc anywhere) ------------
__device__ __nv_bfloat16 g_TEh[MAXN * IN_DIM];
__device__ __nv_bfloat16 g_TEl[MAXN * IN_DIM];
__device__ __nv_bfloat16 g_Xh [MAXN * IN_DIM];
__device__ __nv_bfloat16 g_Xl [MAXN * IN_DIM];
__device__ __nv_bfloat16 g_AGh[MAXN * OUT_DIM];
__device__ __nv_bfloat16 g_AGl[MAXN * OUT_DIM];
__device__ __nv_bfloat16 g_Wh [4 * OUT_DIM * IN_DIM];
__device__ __nv_bfloat16 g_Wl [4 * OUT_DIM * IN_DIM];
__device__ __half g_Qh [MAXN * OUT_DIM];
__device__ __half g_Krh[MAXN * OUT_DIM];
__device__ __half g_Vh [MAXN * OUT_DIM];
__device__ int   g_deg[MAXN];
__device__ int   g_ptr[MAXN + 1];
__device__ int   g_cur[MAXN];
__device__ int   g_src[MAXE];
__device__ int   g_bsum[128];

// ---------------- asm helpers (family-common: sm_80+) -------------------------
__device__ __forceinline__ uint32_t smem_u32(const void* p) {
    uint32_t a;
    asm("{ .reg .u64 t; cvta.to.shared.u64 t, %1; cvt.u32.u64 %0, t; }"
        : "=r"(a) : "l"(p));
    return a;
}
__device__ __forceinline__ void cp16(uint32_t dst, const void* src, uint32_t bytes) {
    asm volatile("cp.async.cg.shared.global [%0], [%1], 16, %2;"
                 :: "r"(dst), "l"(src), "r"(bytes));
}
#define CP_COMMIT() asm volatile("cp.async.commit_group;" ::: "memory")
#define CP_WAIT(n)  asm volatile("cp.async.wait_group %0;" :: "n"(n) : "memory")

__device__ __forceinline__ void ldm_x4(uint32_t* r, uint32_t addr) {
    asm volatile("ldmatrix.sync.aligned.m8n8.x4.shared.b16 {%0,%1,%2,%3}, [%4];"
                 : "=r"(r[0]), "=r"(r[1]), "=r"(r[2]), "=r"(r[3]) : "r"(addr));
}
__device__ __forceinline__ void ldm_x2(uint32_t* r, uint32_t addr) {
    asm volatile("ldmatrix.sync.aligned.m8n8.x2.shared.b16 {%0,%1}, [%2];"
                 : "=r"(r[0]), "=r"(r[1]) : "r"(addr));
}
__device__ __forceinline__ void mma_bf16(float* c, const uint32_t* a, const uint32_t* b) {
    asm volatile("mma.sync.aligned.m16n8k16.row.col.f32.bf16.bf16.f32 "
                 "{%0,%1,%2,%3}, {%4,%5,%6,%7}, {%8,%9}, {%0,%1,%2,%3};"
                 : "+f"(c[0]), "+f"(c[1]), "+f"(c[2]), "+f"(c[3])
                 : "r"(a[0]), "r"(a[1]), "r"(a[2]), "r"(a[3]), "r"(b[0]), "r"(b[1]));
}

// ---------------- split-bf16 conversion kernels -------------------------------
__device__ __forceinline__ void split2(float x, float y,
                                       __nv_bfloat162& hi, __nv_bfloat162& lo) {
    __nv_bfloat16 hx = __float2bfloat16(x), hy = __float2bfloat16(y);
    __nv_bfloat16 lx = __float2bfloat16(x - __bfloat162float(hx));
    __nv_bfloat16 ly = __float2bfloat16(y - __bfloat162float(hy));
    hi = __nv_bfloat162(hx, hy);
    lo = __nv_bfloat162(lx, ly);
}
__global__ void cvt_split_kernel(const float4* __restrict__ src,
                                 __nv_bfloat162* __restrict__ hi,
                                 __nv_bfloat162* __restrict__ lo, int n4) {
    for (int i = blockIdx.x * blockDim.x + threadIdx.x; i < n4;
         i += gridDim.x * blockDim.x) {
        float4 v = src[i];
        split2(v.x, v.y, hi[2 * i],     lo[2 * i]);
        split2(v.z, v.w, hi[2 * i + 1], lo[2 * i + 1]);
    }
}
__global__ void cvt_split_te_kernel(const float4* __restrict__ user,
                                    const float4* __restrict__ item,
                                    int nu4, int total4) {
    __nv_bfloat162* hi = reinterpret_cast<__nv_bfloat162*>(g_TEh);
    __nv_bfloat162* lo = reinterpret_cast<__nv_bfloat162*>(g_TEl);
    for (int i = blockIdx.x * blockDim.x + threadIdx.x; i < total4;
         i += gridDim.x * blockDim.x) {
        float4 v = (i < nu4) ? user[i] : item[i - nu4];
        split2(v.x, v.y, hi[2 * i],     lo[2 * i]);
        split2(v.z, v.w, hi[2 * i + 1], lo[2 * i + 1]);
    }
}
// all 4 weight matrices in one launch (each 65536 floats = 16384 float4)
__global__ void cvt_split_w4_kernel(const float4* __restrict__ W0,
                                    const float4* __restrict__ W1,
                                    const float4* __restrict__ W2,
                                    const float4* __restrict__ W3) {
    __nv_bfloat162* hi = reinterpret_cast<__nv_bfloat162*>(g_Wh);
    __nv_bfloat162* lo = reinterpret_cast<__nv_bfloat162*>(g_Wl);
    const float4* Ws[4] = {W0, W1, W2, W3};
    for (int i = blockIdx.x * blockDim.x + threadIdx.x; i < 65536;
         i += gridDim.x * blockDim.x) {
        float4 v = Ws[i >> 14][i & 16383];
        split2(v.x, v.y, hi[2 * i],     lo[2 * i]);
        split2(v.z, v.w, hi[2 * i + 1], lo[2 * i + 1]);
    }
}

// ---------------- CSR build ----------------------------------------------------
__global__ void zero_deg_kernel(int n) {
    for (int i = blockIdx.x * blockDim.x + threadIdx.x; i < n;
         i += gridDim.x * blockDim.x)
        g_deg[i] = 0;
}
__global__ void count_kernel(const int* __restrict__ col, int E) {
    for (int e = blockIdx.x * blockDim.x + threadIdx.x; e < E;
         e += gridDim.x * blockDim.x)
        atomicAdd(&g_deg[col[e]], 1);
}
__global__ void scan_partial_kernel(int n) {
    __shared__ int sh[1024];
    int i = blockIdx.x * 1024 + threadIdx.x;
    int v = (i < n) ? g_deg[i] : 0;
    sh[threadIdx.x] = v;
    __syncthreads();
    for (int off = 1; off < 1024; off <<= 1) {
        int t = (threadIdx.x >= off) ? sh[threadIdx.x - off] : 0;
        __syncthreads();
        sh[threadIdx.x] += t;
        __syncthreads();
    }
    if (i < n) g_ptr[i] = sh[threadIdx.x] - v;
    if (threadIdx.x == 1023) g_bsum[blockIdx.x] = sh[1023];
}
__global__ void scan_bsums_kernel(int nb) {
    if (threadIdx.x == 0) {
        int s = 0;
        for (int b = 0; b < nb; b++) { int t = g_bsum[b]; g_bsum[b] = s; s += t; }
    }
}
__global__ void scan_add_kernel(int n, int E) {
    int i = blockIdx.x * blockDim.x + threadIdx.x;
    if (i < n) {
        int p = g_ptr[i] + g_bsum[i >> 10];
        g_ptr[i] = p;
        g_cur[i] = p;
    }
    if (i == 0) g_ptr[n] = E;
}
__global__ void scatter_kernel(const int* __restrict__ row,
                               const int* __restrict__ col, int E) {
    for (int e = blockIdx.x * blockDim.x + threadIdx.x; e < E;
         e += gridDim.x * blockDim.x) {
        int pos = atomicAdd(&g_cur[col[e]], 1);
        g_src[pos] = row[e];
    }
}

// ---------------- 3M-split bf16 HMMA GEMM -------------------------------------
// Logical K = 768 (Ah*Wh, Ah*Wl, Al*Wh), 12 k-tiles of 64. CTA 128x128, 8 warps.
// Output: fp32 C if Ch==nullptr, else fp16 Ch.
#define NKT 12
#define GEMM_SMEM (4 * 16384)

__global__ void __launch_bounds__(256, 2)
gemm3m_kernel(const __nv_bfloat16* __restrict__ Ah, const __nv_bfloat16* __restrict__ Al,
              const __nv_bfloat16* __restrict__ Wh, const __nv_bfloat16* __restrict__ Wl,
              const float* __restrict__ bias, const float* __restrict__ bias2,
              float* __restrict__ C, __half* __restrict__ Ch, int M) {
    extern __shared__ char smem[];
    const uint32_t sb = smem_u32(smem);
    const int tid = threadIdx.x, wid = tid >> 5, lid = tid & 31;
    const int bm = blockIdx.x * 128;
    const int bn = blockIdx.y * 128;
    const int wm = (wid >> 2) * 64;
    const int wn = (wid & 3) * 32;

    float acc[4][4][4];
#pragma unroll
    for (int i = 0; i < 4; i++)
#pragma unroll
        for (int j = 0; j < 4; j++)
#pragma unroll
            for (int k = 0; k < 4; k++) acc[i][j][k] = 0.f;

    auto load_tile = [&](int kt, int stage) {
        const int seg = kt >> 2;
        const int koff = (kt & 3) * 64;
        const __nv_bfloat16* As = (seg == 2) ? Al : Ah;
        const __nv_bfloat16* Ws = (seg == 1) ? Wl : Wh;
        const uint32_t uA = sb + stage * 16384;
        const uint32_t uB = sb + 32768 + stage * 16384;
#pragma unroll
        for (int i = tid; i < 1024; i += 256) {
            int r = i >> 3, c = i & 7;
            int grow = bm + r;
            const char* g = (const char*)As + (size_t)grow * 512 + koff * 2 + c * 16;
            uint32_t d = uA + r * 128 + ((c ^ (r & 7)) << 4);
            cp16(d, g, (grow < M) ? 16u : 0u);
        }
#pragma unroll
        for (int i = tid; i < 1024; i += 256) {
            int r = i >> 3, c = i & 7;
            const char* g = (const char*)Ws + (size_t)(bn + r) * 512 + koff * 2 + c * 16;
            uint32_t d = uB + r * 128 + ((c ^ (r & 7)) << 4);
            cp16(d, g, 16u);
        }
        CP_COMMIT();
    };

    load_tile(0, 0);

    for (int kt = 0; kt < NKT; kt++) {
        const int st = kt & 1;
        if (kt + 1 < NKT) {
            load_tile(kt + 1, (kt + 1) & 1);
            CP_WAIT(1);
        } else {
            CP_WAIT(0);
        }
        __syncthreads();

        const uint32_t uA = sb + st * 16384;
        const uint32_t uB = sb + 32768 + st * 16384;
#pragma unroll
        for (int ks = 0; ks < 4; ks++) {
            uint32_t a[4][4], b[4][2];
#pragma unroll
            for (int ma = 0; ma < 4; ma++) {
                int ar = wm + ma * 16 + (lid & 15);
                int ch = ks * 2 + (lid >> 4);
                ldm_x4(a[ma], uA + ar * 128 + ((ch ^ (ar & 7)) << 4));
            }
#pragma unroll
            for (int na = 0; na < 4; na++) {
                int nr = wn + na * 8 + (lid & 7);
                int ch = ks * 2 + ((lid >> 3) & 1);
                ldm_x2(b[na], uB + nr * 128 + ((ch ^ (nr & 7)) << 4));
            }
#pragma unroll
            for (int ma = 0; ma < 4; ma++)
#pragma unroll
                for (int na = 0; na < 4; na++)
                    mma_bf16(acc[ma][na], a[ma], b[na]);
        }
        __syncthreads();
    }

    const int g = lid >> 2;
    const int tg = (lid & 3) * 2;
#pragma unroll
    for (int ma = 0; ma < 4; ma++) {
        int mr = bm + wm + ma * 16 + g;
#pragma unroll
        for (int na = 0; na < 4; na++) {
            int nc = bn + wn + na * 8 + tg;
            float b0 = bias[nc], b1 = bias[nc + 1];
            if (bias2) { b0 += bias2[nc]; b1 += bias2[nc + 1]; }
            float o00 = acc[ma][na][0] + b0, o01 = acc[ma][na][1] + b1;
            float o10 = acc[ma][na][2] + b0, o11 = acc[ma][na][3] + b1;
            if (Ch) {
                if (mr < M)
                    *(__half2*)(Ch + (size_t)mr * OUT_DIM + nc) = __floats2half2_rn(o00, o01);
                if (mr + 8 < M)
                    *(__half2*)(Ch + (size_t)(mr + 8) * OUT_DIM + nc) = __floats2half2_rn(o10, o11);
            } else {
                if (mr < M)
                    *(float2*)(C + (size_t)mr * OUT_DIM + nc) = make_float2(o00, o01);
                if (mr + 8 < M)
                    *(float2*)(C + (size_t)(mr + 8) * OUT_DIM + nc) = make_float2(o10, o11);
            }
        }
    }
}

// ---------------- per-node attention, fp16 gathers, bf16-split output ---------
// block = node (128 threads). warp w covers heads 2w, 2w+1;
// lanes 0-15 -> first head (2 dims/lane), lanes 16-31 -> second head.
__global__ void __launch_bounds__(128)
attn_kernel(int N) {
    const int n = blockIdx.x;
    if (n >= N) return;
    const int tid = threadIdx.x;
    const int w = tid >> 5, lid = tid & 31;
    const int head = w * 2 + (lid >> 4);
    const int sl = lid & 15;                 // half2 index within head
    const int h2off = head * 16 + sl;        // half2 offset within a row (128 half2)
    const int beg = g_ptr[n];
    const int end = g_ptr[n + 1];

    const __half2* Qh2  = reinterpret_cast<const __half2*>(g_Qh);
    const __half2* Krh2 = reinterpret_cast<const __half2*>(g_Krh);
    const __half2* Vh2  = reinterpret_cast<const __half2*>(g_Vh);

    const float2 qf = __half22float2(Qh2[(size_t)n * 128 + h2off]);
    const float inv_sqrt_dk = 0.17677669529663689f;

    float m = -INFINITY, s = 0.f;
    float ax = 0.f, ay = 0.f;

    for (int i = beg; i < end; i++) {
        int r = g_src[i];
        float2 kf = __half22float2(Krh2[(size_t)r * 128 + h2off]);
        float2 vf = __half22float2(Vh2[(size_t)r * 128 + h2off]);
        float p = qf.x * kf.x + qf.y * kf.y;
        p += __shfl_xor_sync(0xffffffffu, p, 8);
        p += __shfl_xor_sync(0xffffffffu, p, 4);
        p += __shfl_xor_sync(0xffffffffu, p, 2);
        p += __shfl_xor_sync(0xffffffffu, p, 1);
        float xsc = p * inv_sqrt_dk;
        float nm = fmaxf(m, xsc);
        float scale = __expf(m - nm);
        float ex = __expf(xsc - nm);
        s = s * scale + ex;
        ax = ax * scale + ex * vf.x;
        ay = ay * scale + ex * vf.y;
        m = nm;
    }

    float ox = 0.f, oy = 0.f;
    if (s > 0.f) { float inv = 1.f / s; ox = ax * inv; oy = ay * inv; }
    __nv_bfloat162 hi, lo;
    split2(ox, oy, hi, lo);
    reinterpret_cast<__nv_bfloat162*>(g_AGh)[(size_t)n * 128 + h2off] = hi;
    reinterpret_cast<__nv_bfloat162*>(g_AGl)[(size_t)n * 128 + h2off] = lo;
}

// ---------------- launch --------------------------------------------------------
extern "C" void kernel_launch(void* const* d_in, const int* in_sizes, int n_in,
                              void* d_out, int out_size) {
    const float* x    = (const float*)d_in[0];
    const int*   row  = (const int*)  d_in[1];
    const int*   col  = (const int*)  d_in[2];
    const float* rel  = (const float*)d_in[3];
    const float* user = (const float*)d_in[4];
    const float* item = (const float*)d_in[5];
    const float* Wq   = (const float*)d_in[6];
    const float* bq   = (const float*)d_in[7];
    const float* Wk   = (const float*)d_in[8];
    const float* bk   = (const float*)d_in[9];
    const float* Wv   = (const float*)d_in[10];
    const float* bv   = (const float*)d_in[11];
    const float* Wo   = (const float*)d_in[12];
    const float* bo   = (const float*)d_in[13];
    float* out = (float*)d_out;

    const int N  = in_sizes[0] / IN_DIM;
    const int E  = in_sizes[1];
    const int NU = in_sizes[4] / IN_DIM;

    __half *dQh, *dKrh, *dVh;
    __nv_bfloat16 *dTEh, *dTEl, *dXh, *dXl, *dAGh, *dAGl, *dWh, *dWl;
    cudaGetSymbolAddress((void**)&dQh,  g_Qh);
    cudaGetSymbolAddress((void**)&dKrh, g_Krh);
    cudaGetSymbolAddress((void**)&dVh,  g_Vh);
    cudaGetSymbolAddress((void**)&dTEh, g_TEh);
    cudaGetSymbolAddress((void**)&dTEl, g_TEl);
    cudaGetSymbolAddress((void**)&dXh,  g_Xh);
    cudaGetSymbolAddress((void**)&dXl,  g_Xl);
    cudaGetSymbolAddress((void**)&dAGh, g_AGh);
    cudaGetSymbolAddress((void**)&dAGl, g_AGl);
    cudaGetSymbolAddress((void**)&dWh,  g_Wh);
    cudaGetSymbolAddress((void**)&dWl,  g_Wl);

    cudaFuncSetAttribute(gemm3m_kernel,
                         cudaFuncAttributeMaxDynamicSharedMemorySize, GEMM_SMEM);

    // 1. split-bf16 conversions
    {
        int total4 = N * (IN_DIM / 4);
        int nu4 = NU * (IN_DIM / 4);
        cvt_split_te_kernel<<<1024, 256>>>((const float4*)user, (const float4*)item,
                                           nu4, total4);
        cvt_split_kernel<<<1024, 256>>>((const float4*)x,
                                        (__nv_bfloat162*)dXh, (__nv_bfloat162*)dXl,
                                        total4);
        cvt_split_w4_kernel<<<256, 256>>>((const float4*)Wq, (const float4*)Wk,
                                          (const float4*)Wv, (const float4*)Wo);
    }

    // 2. CSR build by destination (col)
    zero_deg_kernel<<<(N + 255) / 256, 256>>>(N);
    count_kernel<<<(E + 255) / 256, 256>>>(col, E);
    int nb = (N + 1023) / 1024;
    scan_partial_kernel<<<nb, 1024>>>(N);
    scan_bsums_kernel<<<1, 32>>>(nb);
    scan_add_kernel<<<(N + 255) / 256, 256>>>(N, E);
    scatter_kernel<<<(E + 255) / 256, 256>>>(row, col, E);

    // 3. projections (3M-split HMMA) -> fp16 intermediates
    dim3 gg((N + 127) / 128, 2);
    gemm3m_kernel<<<gg, 256, GEMM_SMEM>>>(dTEh, dTEl, dWh + 0 * 65536, dWl + 0 * 65536,
                                          bq, nullptr, nullptr, dQh,  N);
    gemm3m_kernel<<<gg, 256, GEMM_SMEM>>>(dTEh, dTEl, dWh + 1 * 65536, dWl + 1 * 65536,
                                          bk, rel,     nullptr, dKrh, N);
    gemm3m_kernel<<<gg, 256, GEMM_SMEM>>>(dXh,  dXl,  dWh + 2 * 65536, dWl + 2 * 65536,
                                          bv, nullptr, nullptr, dVh,  N);

    // 4. attention (fp16 gathers, writes bf16 hi/lo split directly)
    attn_kernel<<<N, 128>>>(N);

    // 5. output projection -> fp32 out
    gemm3m_kernel<<<gg, 256, GEMM_SMEM>>>(dAGh, dAGl, dWh + 3 * 65536, dWl + 3 * 65536,
                                          bo, nullptr, out, nullptr, N);
}